// round 1
// baseline (speedup 1.0000x reference)
#include <cuda_runtime.h>
#include <math.h>
#include <stdint.h>
#include <stddef.h>

// ---------------- problem constants ----------------
#define Bv      16
#define Kv      2
#define Ev      768
#define Hv      12
#define HSv     64
#define Lv      12
#define Tv      621          // 32 + 196 + 392 + 1
#define SLD     624          // padded score row stride (16B-aligned)
#define NPATCH  588          // 196 goal-img + 392 img patches per batch
#define QKVLD   2304         // 3 * E
#define E4      3072         // 4 * E
#define AOUTv   64
#define SCALE_QK 0.036084391824351615f  // 768^-0.5

#define CDIV(a,b) (((a)+(b)-1)/(b))

// ---------------- scratch (device globals; no allocation allowed) ----------------
__device__ float g_POS[Tv*Ev];
__device__ float g_W  [(size_t)Lv*Ev*QKVLD];            // fused [e][3*H*HS] qkv weights per layer
__device__ float g_Xp [(size_t)Bv*NPATCH*Ev];           // gathered patches
__device__ float g_X  [(size_t)Bv*Tv*Ev];               // residual stream
__device__ float g_Hb [(size_t)Bv*Tv*Ev];               // LN output
__device__ float g_QKV[(size_t)Bv*Tv*QKVLD];            // [b][t][q|k|v, h, d]
__device__ float g_S  [(size_t)Bv*Hv*Tv*SLD];           // attention scores / probs (padded cols stay 0)
__device__ float g_O  [(size_t)Bv*Tv*Ev];               // attention output, head-major cols
__device__ float g_F  [(size_t)Bv*Tv*E4];               // FF intermediate
__device__ float g_Z  [Bv*Ev];                          // head hidden

// ---------------- mask (matches numpy construction order) ----------------
__device__ __forceinline__ bool keep_fn(int t, int s) {
    bool v = (t == s);
    if (s < 32) v = !(t >= 32 && t < 228);          // all see text, except goal-img rows
    if (t >= 228 && s >= 228 && s < 424) v = true;  // ik = 0
    if (t >= 424 && s >= 424 && s < 620) v = true;  // ik = 1
    return v;
}

// ---------------- positional embedding (float64 math, matches reference) ----------------
__global__ void pos_kernel(float* POS) {
    int idx = blockIdx.x * 256 + threadIdx.x;
    if (idx >= Tv * Ev) return;
    int t = idx / Ev, j = idx % Ev;
    double expo = (double)(j & ~1) / (double)Ev;
    double ang  = (double)t / pow(10000.0, expo);
    POS[idx] = (float)((j & 1) ? cos(ang) : sin(ang));
}

// ---------------- fuse wq/wk/wv [l][h][e][d] -> W[l][e][which*768 + h*64 + d] ----------------
__global__ void build_w(const float* __restrict__ wq, const float* __restrict__ wk,
                        const float* __restrict__ wv, float* __restrict__ W) {
    int idx = blockIdx.x * 256 + threadIdx.x;
    if (idx >= Lv * Ev * QKVLD) return;
    int col = idx % QKVLD;
    int e   = (idx / QKVLD) % Ev;
    int l   = idx / (QKVLD * Ev);
    int which = col / Ev;
    int hd    = col % Ev;
    int h = hd / HSv, d = hd % HSv;
    const float* src = (which == 0) ? wq : (which == 1) ? wk : wv;
    W[idx] = src[(((size_t)l * Hv + h) * Ev + e) * (size_t)HSv + d];
}

// ---------------- gather patches: Xp[b][p][f], p<196 goal img, 196..587 imgs ----------------
__global__ void gather_patches(const float* __restrict__ images, const float* __restrict__ goal_imgs,
                               float* __restrict__ Xp) {
    int idx = blockIdx.x * 256 + threadIdx.x;
    if (idx >= Bv * NPATCH * Ev) return;
    int f = idx % Ev;
    int r = idx / Ev;
    int p = r % NPATCH;
    int b = r / NPATCH;
    int py = f / 48, px = (f % 48) / 3, c = f % 3;
    float val;
    if (p < 196) {
        int pr = p / 14, pc = p % 14;
        int y = pr * 16 + py, x = pc * 16 + px;
        val = goal_imgs[(((size_t)b * 224 + y) * 224 + x) * 3 + c];
    } else {
        int q = p - 196;
        int k = q / 196, pp = q % 196;
        int pr = pp / 14, pc = pp % 14;
        int y = pr * 16 + py, x = pc * 16 + px;
        val = images[((((size_t)b * Kv + k) * 224 + y) * 224 + x) * 3 + c];
    }
    Xp[idx] = val;
}

// ---------------- text + action embed (+POS) ----------------
__global__ void embed_txt_act(const int* __restrict__ goals_txt, const float* __restrict__ text_emb,
                              const float* __restrict__ action_emb, const float* __restrict__ POS,
                              float* __restrict__ X) {
    int idx = blockIdx.x * 256 + threadIdx.x;
    if (idx >= Bv * 33 * Ev) return;
    int e  = idx % Ev;
    int r  = idx / Ev;
    int tt = r % 33;
    int b  = r / 33;
    int t  = (tt < 32) ? tt : 620;
    float v = (tt < 32) ? text_emb[(size_t)goals_txt[b * 32 + tt] * Ev + e] : action_emb[e];
    X[((size_t)b * Tv + t) * Ev + e] = v + POS[(size_t)t * Ev + e];
}

// ---------------- layernorm: block per row ----------------
__global__ void ln_kernel(const float* __restrict__ X, float* __restrict__ Out,
                          const float* __restrict__ sc, const float* __restrict__ bi) {
    int row = blockIdx.x;
    const float* x = X + (size_t)row * Ev;
    float* o = Out + (size_t)row * Ev;
    __shared__ float r1[256], r2[256];
    int tid = threadIdx.x;
    float s = 0.f, ss = 0.f;
    for (int e = tid; e < Ev; e += 256) { float v = x[e]; s += v; ss += v * v; }
    r1[tid] = s; r2[tid] = ss;
    __syncthreads();
    for (int off = 128; off; off >>= 1) {
        if (tid < off) { r1[tid] += r1[tid + off]; r2[tid] += r2[tid + off]; }
        __syncthreads();
    }
    float m   = r1[0] * (1.f / Ev);
    float var = r2[0] * (1.f / Ev) - m * m;
    float inv = 1.f / sqrtf(var + 1e-5f);
    for (int e = tid; e < Ev; e += 256)
        o[e] = (x[e] - m) * inv * sc[e] + bi[e];
}

// ---------------- generic fp32 GEMM: 128x128x8, 8x8 microtile, flexible epilogue ----------------
__global__ void __launch_bounds__(256, 2)
sgemm128(int M, int N, int K,
         const float* __restrict__ A, int lda, size_t sA,
         const float* __restrict__ B, int ldb, size_t sB,
         float* __restrict__ C, int ldc, size_t sC,
         const float* __restrict__ bias,
         const float* __restrict__ rowmat, int ldrm,
         int accflag, int reluflag)
{
    __shared__ __align__(16) float As[8][128];
    __shared__ __align__(16) float Bs[8][128];
    int bz = blockIdx.z;
    A += (size_t)bz * sA; B += (size_t)bz * sB; C += (size_t)bz * sC;
    int n0 = blockIdx.x * 128, m0 = blockIdx.y * 128;
    int tid = threadIdx.x;
    int tx = tid & 15, ty = tid >> 4;
    int arow = tid >> 1,  akk  = (tid & 1) * 4;
    int bkk  = tid >> 5,  bcol = (tid & 31) * 4;
    bool aval = (m0 + arow) < M;
    bool bval = (n0 + bcol) < N;
    const float* Aptr = A + (size_t)(m0 + arow) * lda + akk;
    const float* Bptr = B + (size_t)bkk * ldb + n0 + bcol;

    float acc[8][8];
    #pragma unroll
    for (int i = 0; i < 8; i++)
        #pragma unroll
        for (int j = 0; j < 8; j++) acc[i][j] = 0.f;

    for (int k0 = 0; k0 < K; k0 += 8) {
        float4 av = make_float4(0.f,0.f,0.f,0.f), bv = make_float4(0.f,0.f,0.f,0.f);
        if (aval) av = *(const float4*)(Aptr + k0);
        if (bval) bv = *(const float4*)(Bptr + (size_t)k0 * ldb);
        __syncthreads();
        As[akk+0][arow] = av.x; As[akk+1][arow] = av.y;
        As[akk+2][arow] = av.z; As[akk+3][arow] = av.w;
        *(float4*)&Bs[bkk][bcol] = bv;
        __syncthreads();
        #pragma unroll
        for (int kk = 0; kk < 8; kk++) {
            float a[8], b[8];
            *(float4*)(a)   = *(const float4*)&As[kk][ty*8];
            *(float4*)(a+4) = *(const float4*)&As[kk][ty*8+4];
            *(float4*)(b)   = *(const float4*)&Bs[kk][tx*8];
            *(float4*)(b+4) = *(const float4*)&Bs[kk][tx*8+4];
            #pragma unroll
            for (int i = 0; i < 8; i++)
                #pragma unroll
                for (int j = 0; j < 8; j++)
                    acc[i][j] += a[i] * b[j];
        }
    }

    #pragma unroll
    for (int i = 0; i < 8; i++) {
        int r = m0 + ty*8 + i;
        if (r >= M) continue;
        #pragma unroll
        for (int j = 0; j < 8; j++) {
            int c = n0 + tx*8 + j;
            if (c >= N) continue;
            float v = acc[i][j];
            if (bias)   v += bias[c];
            if (rowmat) v += rowmat[(size_t)r * ldrm + c];
            if (accflag) v += C[(size_t)r * ldc + c];
            if (reluflag) v = fmaxf(v, 0.f);
            C[(size_t)r * ldc + c] = v;
        }
    }
}

// ---------------- QK^T: 64x64 tile per (b,h), d=64 contraction ----------------
__global__ void qk_kernel(const float* __restrict__ QKV, float* __restrict__ S) {
    int bh = blockIdx.z;
    int b = bh / Hv, h = bh % Hv;
    int t0 = blockIdx.y * 64, s0 = blockIdx.x * 64;
    __shared__ __align__(16) float Qs[64][64];  // [d][t]
    __shared__ __align__(16) float Ks[64][64];  // [d][s]
    const float* Qp = QKV + (size_t)b * Tv * QKVLD + h * HSv;
    const float* Kp = Qp + Ev;
    int tid = threadIdx.x;
    int row = tid >> 2, dseg = (tid & 3) * 16;
    #pragma unroll
    for (int i = 0; i < 16; i += 4) {
        float4 v = make_float4(0.f,0.f,0.f,0.f);
        if (t0 + row < Tv) v = *(const float4*)(Qp + (size_t)(t0 + row) * QKVLD + dseg + i);
        Qs[dseg+i+0][row]=v.x; Qs[dseg+i+1][row]=v.y; Qs[dseg+i+2][row]=v.z; Qs[dseg+i+3][row]=v.w;
        float4 w = make_float4(0.f,0.f,0.f,0.f);
        if (s0 + row < Tv) w = *(const float4*)(Kp + (size_t)(s0 + row) * QKVLD + dseg + i);
        Ks[dseg+i+0][row]=w.x; Ks[dseg+i+1][row]=w.y; Ks[dseg+i+2][row]=w.z; Ks[dseg+i+3][row]=w.w;
    }
    __syncthreads();
    int tx = tid & 15, ty = tid >> 4;
    float acc[4][4];
    #pragma unroll
    for (int i=0;i<4;i++) { acc[i][0]=0.f; acc[i][1]=0.f; acc[i][2]=0.f; acc[i][3]=0.f; }
    #pragma unroll 8
    for (int d = 0; d < 64; d++) {
        float4 qa = *(const float4*)&Qs[d][ty*4];
        float4 kb = *(const float4*)&Ks[d][tx*4];
        float qv[4] = {qa.x,qa.y,qa.z,qa.w};
        float kv[4] = {kb.x,kb.y,kb.z,kb.w};
        #pragma unroll
        for (int i=0;i<4;i++)
            #pragma unroll
            for (int j=0;j<4;j++) acc[i][j] += qv[i]*kv[j];
    }
    float* Sp = S + (size_t)bh * Tv * SLD;
    #pragma unroll
    for (int i=0;i<4;i++) {
        int t = t0 + ty*4 + i;
        if (t >= Tv) continue;
        #pragma unroll
        for (int j=0;j<4;j++) {
            int s = s0 + tx*4 + j;
            if (s >= Tv) continue;
            Sp[(size_t)t * SLD + s] = acc[i][j] * SCALE_QK;
        }
    }
}

// ---------------- masked softmax (in place over S rows) ----------------
__global__ void softmax_kernel(float* __restrict__ S) {
    int t = blockIdx.x, bh = blockIdx.y;
    float* row = S + ((size_t)bh * Tv + t) * SLD;
    __shared__ float red[128];
    int tid = threadIdx.x;
    float mx = -3.0e38f;
    for (int s = tid; s < Tv; s += 128)
        if (keep_fn(t, s)) mx = fmaxf(mx, row[s]);
    red[tid] = mx; __syncthreads();
    for (int off = 64; off; off >>= 1) {
        if (tid < off) red[tid] = fmaxf(red[tid], red[tid + off]);
        __syncthreads();
    }
    mx = red[0]; __syncthreads();
    float sm = 0.f;
    for (int s = tid; s < Tv; s += 128) {
        float p = keep_fn(t, s) ? expf(row[s] - mx) : 0.f;
        row[s] = p;
        sm += p;
    }
    red[tid] = sm; __syncthreads();
    for (int off = 64; off; off >>= 1) {
        if (tid < off) red[tid] += red[tid + off];
        __syncthreads();
    }
    float inv = 1.f / red[0];
    for (int s = tid; s < Tv; s += 128) row[s] *= inv;
}

// ---------------- P @ V: 64(t) x 64(d), K=621 in chunks of 16 ----------------
__global__ void pv_kernel(const float* __restrict__ S, const float* __restrict__ QKV,
                          float* __restrict__ O) {
    int bh = blockIdx.y;
    int b = bh / Hv, h = bh % Hv;
    int t0 = blockIdx.x * 64;
    __shared__ __align__(16) float Ps[16][68];  // [s][t]
    __shared__ __align__(16) float Vs[16][68];  // [s][d]
    const float* Sp = S + (size_t)bh * Tv * SLD;
    const float* Vp = QKV + (size_t)b * Tv * QKVLD + 2 * Ev + h * HSv;
    int tid = threadIdx.x;
    int tr = tid >> 2,  sseg = (tid & 3) * 4;
    int sr = tid >> 4,  dcol = (tid & 15) * 4;
    int tx = tid & 15,  ty = tid >> 4;
    float acc[4][4];
    #pragma unroll
    for (int i=0;i<4;i++){ acc[i][0]=0.f; acc[i][1]=0.f; acc[i][2]=0.f; acc[i][3]=0.f; }

    for (int c0 = 0; c0 < Tv; c0 += 16) {
        float4 pv = make_float4(0.f,0.f,0.f,0.f);
        if (t0 + tr < Tv)  // padded cols (>=621) are permanently 0, safe to read
            pv = *(const float4*)(Sp + (size_t)(t0 + tr) * SLD + c0 + sseg);
        float4 vv = make_float4(0.f,0.f,0.f,0.f);
        if (c0 + sr < Tv)
            vv = *(const float4*)(Vp + (size_t)(c0 + sr) * QKVLD + dcol);
        __syncthreads();
        Ps[sseg+0][tr]=pv.x; Ps[sseg+1][tr]=pv.y; Ps[sseg+2][tr]=pv.z; Ps[sseg+3][tr]=pv.w;
        *(float4*)&Vs[sr][dcol] = vv;
        __syncthreads();
        #pragma unroll
        for (int ss = 0; ss < 16; ss++) {
            float4 pa = *(const float4*)&Ps[ss][ty*4];
            float4 vb = *(const float4*)&Vs[ss][tx*4];
            float pr[4] = {pa.x,pa.y,pa.z,pa.w};
            float vr[4] = {vb.x,vb.y,vb.z,vb.w};
            #pragma unroll
            for (int i=0;i<4;i++)
                #pragma unroll
                for (int j=0;j<4;j++) acc[i][j] += pr[i]*vr[j];
        }
        __syncthreads();
    }
    #pragma unroll
    for (int i=0;i<4;i++) {
        int t = t0 + ty*4 + i;
        if (t >= Tv) continue;
        #pragma unroll
        for (int j=0;j<4;j++)
            O[((size_t)b * Tv + t) * Ev + h * HSv + tx*4 + j] = acc[i][j];
    }
}

// ---------------- launch ----------------
extern "C" void kernel_launch(void* const* d_in, const int* in_sizes, int n_in,
                              void* d_out, int out_size) {
    const float* images     = (const float*)d_in[0];
    const int*   goals_txt  = (const int*)  d_in[1];
    const float* goal_imgs  = (const float*)d_in[2];
    const float* patch_w    = (const float*)d_in[3];
    const float* patch_b    = (const float*)d_in[4];
    const float* text_emb   = (const float*)d_in[5];
    const float* action_emb = (const float*)d_in[6];
    const float* wq         = (const float*)d_in[7];
    const float* wk         = (const float*)d_in[8];
    const float* wv         = (const float*)d_in[9];
    const float* proj_w     = (const float*)d_in[10];
    const float* proj_b     = (const float*)d_in[11];
    const float* ln1_s      = (const float*)d_in[12];
    const float* ln1_b      = (const float*)d_in[13];
    const float* ln2_s      = (const float*)d_in[14];
    const float* ln2_b      = (const float*)d_in[15];
    const float* ff_w1      = (const float*)d_in[16];
    const float* ff_b1      = (const float*)d_in[17];
    const float* ff_w2      = (const float*)d_in[18];
    const float* ff_b2      = (const float*)d_in[19];
    const float* hw1        = (const float*)d_in[20];
    const float* hb1        = (const float*)d_in[21];
    const float* hw2        = (const float*)d_in[22];
    const float* hb2        = (const float*)d_in[23];
    float* out = (float*)d_out;

    float *pPOS,*pW,*pXp,*pX,*pH,*pQKV,*pS,*pO,*pF,*pZ;
    cudaGetSymbolAddress((void**)&pPOS, g_POS);
    cudaGetSymbolAddress((void**)&pW,   g_W);
    cudaGetSymbolAddress((void**)&pXp,  g_Xp);
    cudaGetSymbolAddress((void**)&pX,   g_X);
    cudaGetSymbolAddress((void**)&pH,   g_Hb);
    cudaGetSymbolAddress((void**)&pQKV, g_QKV);
    cudaGetSymbolAddress((void**)&pS,   g_S);
    cudaGetSymbolAddress((void**)&pO,   g_O);
    cudaGetSymbolAddress((void**)&pF,   g_F);
    cudaGetSymbolAddress((void**)&pZ,   g_Z);

    const int MT = Bv * Tv;  // 9936

    pos_kernel    <<<CDIV(Tv*Ev, 256), 256>>>(pPOS);
    build_w       <<<CDIV(Lv*Ev*QKVLD, 256), 256>>>(wq, wk, wv, pW);
    gather_patches<<<CDIV(Bv*NPATCH*Ev, 256), 256>>>(images, goal_imgs, pXp);
    embed_txt_act <<<CDIV(Bv*33*Ev, 256), 256>>>(goals_txt, text_emb, action_emb, pPOS, pX);

    // patch embed -> residual stream rows 32..619 (+bias +POS), batched over b
    sgemm128<<<dim3(Ev/128, CDIV(NPATCH,128), Bv), 256>>>(
        NPATCH, Ev, Ev,
        pXp, Ev, (size_t)NPATCH*Ev,
        patch_w, Ev, 0,
        pX + 32*Ev, Ev, (size_t)Tv*Ev,
        patch_b, pPOS + 32*Ev, Ev, 0, 0);

    for (int l = 0; l < Lv; l++) {
        ln_kernel<<<MT, 256>>>(pX, pH, ln1_s + l*Ev, ln1_b + l*Ev);

        sgemm128<<<dim3(QKVLD/128, CDIV(MT,128), 1), 256>>>(
            MT, QKVLD, Ev,
            pH, Ev, 0,
            pW + (size_t)l*Ev*QKVLD, QKVLD, 0,
            pQKV, QKVLD, 0,
            nullptr, nullptr, 0, 0, 0);

        qk_kernel     <<<dim3(10, 10, Bv*Hv), 256>>>(pQKV, pS);
        softmax_kernel<<<dim3(Tv, Bv*Hv), 128>>>(pS);
        pv_kernel     <<<dim3(10, Bv*Hv), 256>>>(pS, pQKV, pO);

        sgemm128<<<dim3(Ev/128, CDIV(MT,128), 1), 256>>>(   // x += O @ proj + b
            MT, Ev, Ev,
            pO, Ev, 0,
            proj_w + (size_t)l*Ev*Ev, Ev, 0,
            pX, Ev, 0,
            proj_b + l*Ev, nullptr, 0, 1, 0);

        ln_kernel<<<MT, 256>>>(pX, pH, ln2_s + l*Ev, ln2_b + l*Ev);

        sgemm128<<<dim3(E4/128, CDIV(MT,128), 1), 256>>>(   // F = relu(h @ W1 + b1)
            MT, E4, Ev,
            pH, Ev, 0,
            ff_w1 + (size_t)l*Ev*E4, E4, 0,
            pF, E4, 0,
            ff_b1 + l*E4, nullptr, 0, 0, 1);

        sgemm128<<<dim3(Ev/128, CDIV(MT,128), 1), 256>>>(   // x += F @ W2 + b2
            MT, Ev, E4,
            pF, E4, 0,
            ff_w2 + (size_t)l*E4*Ev, Ev, 0,
            pX, Ev, 0,
            ff_b2 + l*Ev, nullptr, 0, 1, 0);
    }

    // head: z = x[:,620]; out = relu(z@hw1+hb1)@hw2 + hb2
    sgemm128<<<dim3(Ev/128, 1, 1), 256>>>(
        Bv, Ev, Ev,
        pX + (size_t)620*Ev, Tv*Ev, 0,
        hw1, Ev, 0,
        pZ, Ev, 0,
        hb1, nullptr, 0, 0, 1);

    sgemm128<<<dim3(1, 1, 1), 256>>>(
        Bv, AOUTv, Ev,
        pZ, Ev, 0,
        hw2, AOUTv, 0,
        out, AOUTv, 0,
        hb2, nullptr, 0, 0, 0);

    (void)in_sizes; (void)n_in; (void)out_size;
}

// round 3
// speedup vs baseline: 1.3628x; 1.3628x over previous
#include <cuda_runtime.h>
#include <cuda_bf16.h>
#include <math.h>
#include <stdint.h>
#include <stddef.h>

// ---------------- problem constants ----------------
#define Bv      16
#define Kv      2
#define Ev      768
#define Hv      12
#define HSv     64
#define Lv      12
#define Tv      621
#define SLD     624
#define NPATCH  588
#define QKVLD   2304
#define E4      3072
#define AOUTv   64
#define MTv     (Bv*Tv)      // 9936
#define MPATCH  (Bv*NPATCH)  // 9408
#define SCALE_QK 0.036084391824351615f

#define CDIV(a,b) (((a)+(b)-1)/(b))
#define TGSMEM 65536

typedef __nv_bfloat16 bf16;

// ---------------- scratch ----------------
__device__ __align__(128) float g_POS[Tv*Ev];
__device__ __align__(128) float g_X  [(size_t)MTv*Ev];
__device__ __align__(128) float g_QKV[(size_t)MTv*QKVLD];
__device__ __align__(128) float g_S  [(size_t)Bv*Hv*Tv*SLD];
__device__ __align__(128) float g_Z  [Bv*Ev];

__device__ __align__(128) bf16 g_Hhi [(size_t)MTv*Ev];
__device__ __align__(128) bf16 g_Hlo [(size_t)MTv*Ev];
__device__ __align__(128) bf16 g_Ohi [(size_t)MTv*Ev];
__device__ __align__(128) bf16 g_Olo [(size_t)MTv*Ev];
__device__ __align__(128) bf16 g_Fhi [(size_t)MTv*E4];
__device__ __align__(128) bf16 g_Flo [(size_t)MTv*E4];
__device__ __align__(128) bf16 g_XPhi[(size_t)MPATCH*Ev];
__device__ __align__(128) bf16 g_XPlo[(size_t)MPATCH*Ev];

__device__ __align__(128) bf16 g_Wqkv_h[(size_t)Lv*QKVLD*Ev];
__device__ __align__(128) bf16 g_Wqkv_l[(size_t)Lv*QKVLD*Ev];
__device__ __align__(128) bf16 g_Wprj_h[(size_t)Lv*Ev*Ev];
__device__ __align__(128) bf16 g_Wprj_l[(size_t)Lv*Ev*Ev];
__device__ __align__(128) bf16 g_Wf1_h [(size_t)Lv*E4*Ev];
__device__ __align__(128) bf16 g_Wf1_l [(size_t)Lv*E4*Ev];
__device__ __align__(128) bf16 g_Wf2_h [(size_t)Lv*Ev*E4];
__device__ __align__(128) bf16 g_Wf2_l [(size_t)Lv*Ev*E4];
__device__ __align__(128) bf16 g_Wpat_h[(size_t)Ev*Ev];
__device__ __align__(128) bf16 g_Wpat_l[(size_t)Ev*Ev];

// ---------------- helpers ----------------
__device__ __forceinline__ uint32_t smem_u32(const void* p) {
    uint32_t a;
    asm("{ .reg .u64 t; cvta.to.shared.u64 t, %1; cvt.u32.u64 %0, t; }" : "=r"(a) : "l"(p));
    return a;
}
__device__ __forceinline__ void cp16(uint32_t sa, const void* ga, bool v) {
    int sz = v ? 16 : 0;
    asm volatile("cp.async.cg.shared.global [%0], [%1], 16, %2;" :: "r"(sa), "l"(ga), "r"(sz) : "memory");
}
#define CP_COMMIT() asm volatile("cp.async.commit_group;" ::: "memory")
#define CP_WAIT0()  asm volatile("cp.async.wait_group 0;" ::: "memory")

#define LDSM4(r, a) \
    asm volatile("ldmatrix.sync.aligned.m8n8.x4.shared.b16 {%0,%1,%2,%3}, [%4];" \
        : "=r"((r)[0]),"=r"((r)[1]),"=r"((r)[2]),"=r"((r)[3]) : "r"(a))

__device__ __forceinline__ void mma16816(float* d, const uint32_t* a, const uint32_t* b) {
    asm volatile("mma.sync.aligned.m16n8k16.row.col.f32.bf16.bf16.f32 "
        "{%0,%1,%2,%3}, {%4,%5,%6,%7}, {%8,%9}, {%0,%1,%2,%3};"
        : "+f"(d[0]),"+f"(d[1]),"+f"(d[2]),"+f"(d[3])
        : "r"(a[0]),"r"(a[1]),"r"(a[2]),"r"(a[3]), "r"(b[0]),"r"(b[1]));
}

__device__ __forceinline__ void bf_split(float v, bf16* hi, bf16* lo) {
    bf16 h = __float2bfloat16(v);
    *hi = h;
    *lo = __float2bfloat16(v - __bfloat162float(h));
}

// ---------------- mask ----------------
__device__ __forceinline__ bool keep_fn(int t, int s) {
    bool v = (t == s);
    if (s < 32) v = !(t >= 32 && t < 228);
    if (t >= 228 && s >= 228 && s < 424) v = true;
    if (t >= 424 && s >= 424 && s < 620) v = true;
    return v;
}

// ---------------- positional embedding ----------------
__global__ void pos_kernel(float* POS) {
    int idx = blockIdx.x * 256 + threadIdx.x;
    if (idx >= Tv * Ev) return;
    int t = idx / Ev, j = idx % Ev;
    double expo = (double)(j & ~1) / (double)Ev;
    double ang  = (double)t / pow(10000.0, expo);
    POS[idx] = (float)((j & 1) ? cos(ang) : sin(ang));
}

// ---------------- transpose+convert: src [z][R][C] f32 -> dst [z][C][R] hi/lo bf16 ----------------
__global__ void transpose_conv(const float* __restrict__ src, bf16* __restrict__ dhi,
                               bf16* __restrict__ dlo, int R, int C) {
    __shared__ float t[32][33];
    int z = blockIdx.z;
    src += (size_t)z * R * C; dhi += (size_t)z * R * C; dlo += (size_t)z * R * C;
    int c0 = blockIdx.x * 32, r0 = blockIdx.y * 32;
    int tx = threadIdx.x, ty = threadIdx.y;
    #pragma unroll
    for (int i = 0; i < 4; i++)
        t[ty + 8*i][tx] = src[(size_t)(r0 + ty + 8*i) * C + c0 + tx];
    __syncthreads();
    #pragma unroll
    for (int i = 0; i < 4; i++) {
        float v = t[tx][ty + 8*i];
        size_t o = (size_t)(c0 + ty + 8*i) * R + r0 + tx;
        bf_split(v, dhi + o, dlo + o);
    }
}

// qkv weights: wq/wk/wv [l][h][e][d] -> W[l][n = which*768 + h*64 + d][e]
__global__ void conv_wqkv(const float* __restrict__ wq, const float* __restrict__ wk,
                          const float* __restrict__ wv, bf16* __restrict__ dhi, bf16* __restrict__ dlo) {
    __shared__ float t[32][33];
    int z = blockIdx.z;
    int h = z % Hv, which = (z / Hv) % 3, l = z / (3 * Hv);
    const float* src = (which == 0) ? wq : (which == 1) ? wk : wv;
    src += ((size_t)l * Hv + h) * Ev * HSv;
    int d0 = blockIdx.x * 32, e0 = blockIdx.y * 32;
    int tx = threadIdx.x, ty = threadIdx.y;
    #pragma unroll
    for (int i = 0; i < 4; i++)
        t[ty + 8*i][tx] = src[(size_t)(e0 + ty + 8*i) * HSv + d0 + tx];
    __syncthreads();
    #pragma unroll
    for (int i = 0; i < 4; i++) {
        int d = d0 + ty + 8*i, e = e0 + tx;
        float v = t[tx][ty + 8*i];
        size_t o = ((size_t)l * QKVLD + which * Ev + h * HSv + d) * Ev + e;
        bf_split(v, dhi + o, dlo + o);
    }
}

// ---------------- gather patches -> hi/lo bf16 ----------------
__global__ void gather_patches(const float* __restrict__ images, const float* __restrict__ goal_imgs,
                               bf16* __restrict__ Xhi, bf16* __restrict__ Xlo) {
    int idx = blockIdx.x * 256 + threadIdx.x;
    if (idx >= MPATCH * Ev) return;
    int f = idx % Ev;
    int r = idx / Ev;
    int p = r % NPATCH;
    int b = r / NPATCH;
    int py = f / 48, px = (f % 48) / 3, c = f % 3;
    float val;
    if (p < 196) {
        int pr = p / 14, pc = p % 14;
        int y = pr * 16 + py, x = pc * 16 + px;
        val = goal_imgs[(((size_t)b * 224 + y) * 224 + x) * 3 + c];
    } else {
        int q = p - 196;
        int k = q / 196, pp = q % 196;
        int pr = pp / 14, pc = pp % 14;
        int y = pr * 16 + py, x = pc * 16 + px;
        val = images[((((size_t)b * Kv + k) * 224 + y) * 224 + x) * 3 + c];
    }
    bf_split(val, Xhi + idx, Xlo + idx);
}

// ---------------- text + action embed (+POS) ----------------
__global__ void embed_txt_act(const int* __restrict__ goals_txt, const float* __restrict__ text_emb,
                              const float* __restrict__ action_emb, const float* __restrict__ POS,
                              float* __restrict__ X) {
    int idx = blockIdx.x * 256 + threadIdx.x;
    if (idx >= Bv * 33 * Ev) return;
    int e  = idx % Ev;
    int r  = idx / Ev;
    int tt = r % 33;
    int b  = r / 33;
    int t  = (tt < 32) ? tt : 620;
    float v = (tt < 32) ? text_emb[(size_t)goals_txt[b * 32 + tt] * Ev + e] : action_emb[e];
    X[((size_t)b * Tv + t) * Ev + e] = v + POS[(size_t)t * Ev + e];
}

// ---------------- layernorm -> hi/lo bf16 ----------------
__global__ void ln_kernel(const float* __restrict__ X, bf16* __restrict__ Ohi, bf16* __restrict__ Olo,
                          const float* __restrict__ sc, const float* __restrict__ bi) {
    int row = blockIdx.x;
    const float* x = X + (size_t)row * Ev;
    __shared__ float r1[256], r2[256];
    int tid = threadIdx.x;
    float s = 0.f, ss = 0.f;
    for (int e = tid; e < Ev; e += 256) { float v = x[e]; s += v; ss += v * v; }
    r1[tid] = s; r2[tid] = ss;
    __syncthreads();
    for (int off = 128; off; off >>= 1) {
        if (tid < off) { r1[tid] += r1[tid + off]; r2[tid] += r2[tid + off]; }
        __syncthreads();
    }
    float m   = r1[0] * (1.f / Ev);
    float var = r2[0] * (1.f / Ev) - m * m;
    float inv = 1.f / sqrtf(var + 1e-5f);
    for (int e = tid; e < Ev; e += 256) {
        float v = (x[e] - m) * inv * sc[e] + bi[e];
        size_t o = (size_t)row * Ev + e;
        bf_split(v, Ohi + o, Olo + o);
    }
}

// =====================================================================
// bf16x3 tensor-core GEMM via mma.sync (m16n8k16), 128x128 tile, Kc=32,
// double-buffered cp.async, fused epilogue.
// A: [M][K] hi/lo bf16 row-major; B: [N][K] hi/lo bf16 row-major.
// =====================================================================
__global__ void __launch_bounds__(256, 2)
tgemm(int M, int N, int K,
      const bf16* __restrict__ Ahi, const bf16* __restrict__ Alo,
      const bf16* __restrict__ Bhi, const bf16* __restrict__ Blo,
      const float* __restrict__ bias,
      const float* __restrict__ rowmat, int ldrm, int rmode,
      float* outF, int ldo, int accf, int reluf,
      bf16* outHi, bf16* outLo)
{
    extern __shared__ char sm[];
    uint32_t sbase = smem_u32(sm);
    int tid = threadIdx.x, lane = tid & 31, wid = tid >> 5;
    int m0 = blockIdx.y * 128, n0 = blockIdx.x * 128;
    int wm = wid & 3, wn = wid >> 2;     // warp tile rows: wm*32, cols: wn*64

    float acc[2][8][4];
    #pragma unroll
    for (int i = 0; i < 2; i++)
        #pragma unroll
        for (int j = 0; j < 8; j++)
            #pragma unroll
            for (int q = 0; q < 4; q++) acc[i][j][q] = 0.f;

    int nc = K >> 5;

    // stage layout: +0 Ahi, +8192 Alo, +16384 Bhi, +24576 Blo (each 128 rows x 64B, swizzled)
    auto ld_st = [&](int c, int st) {
        uint32_t sb = sbase + st * 32768;
        int k0 = c * 32;
        #pragma unroll
        for (int h2 = 0; h2 < 2; h2++) {
            int u = h2 * 256 + tid;
            int row = u >> 2, seg = u & 3;
            uint32_t off = (uint32_t)(row * 64 + ((seg ^ ((row >> 1) & 3)) << 4));
            bool av = (m0 + row) < M;
            size_t ao = (size_t)(av ? (m0 + row) : 0) * K + k0 + seg * 8;
            size_t bo = (size_t)(n0 + row) * K + k0 + seg * 8;
            cp16(sb + off,         Ahi + ao, av);
            cp16(sb + 8192  + off, Alo + ao, av);
            cp16(sb + 16384 + off, Bhi + bo, true);
            cp16(sb + 24576 + off, Blo + bo, true);
        }
        CP_COMMIT();
    };

    ld_st(0, 0);

    for (int c = 0; c < nc; c++) {
        int s = c & 1;
        CP_WAIT0();
        __syncthreads();
        if (c + 1 < nc) ld_st(c + 1, 1 - s);

        uint32_t sA_hi = sbase + s * 32768;
        uint32_t sA_lo = sA_hi + 8192;
        uint32_t sB_hi = sA_hi + 16384;
        uint32_t sB_lo = sA_hi + 24576;

        #pragma unroll
        for (int ks = 0; ks < 2; ks++) {
            uint32_t afh[2][4], afl[2][4];
            #pragma unroll
            for (int mt = 0; mt < 2; mt++) {
                int matA = lane >> 3;
                int arow = wm * 32 + mt * 16 + (lane & 7) + (matA & 1) * 8;
                int aseg = ks * 2 + (matA >> 1);
                uint32_t off = (uint32_t)(arow * 64 + ((aseg ^ ((arow >> 1) & 3)) << 4));
                LDSM4(afh[mt], sA_hi + off);
                LDSM4(afl[mt], sA_lo + off);
            }
            #pragma unroll
            for (int np = 0; np < 4; np++) {
                uint32_t bfh[4], bfl[4];
                int matB = lane >> 3;
                int brow = wn * 64 + np * 16 + ((matB >> 1) << 3) + (lane & 7);
                int bseg = ks * 2 + (matB & 1);
                uint32_t boff = (uint32_t)(brow * 64 + ((bseg ^ ((brow >> 1) & 3)) << 4));
                LDSM4(bfh, sB_hi + boff);
                LDSM4(bfl, sB_lo + boff);
                #pragma unroll
                for (int t = 0; t < 2; t++) {
                    int j = np * 2 + t;
                    #pragma unroll
                    for (int mt = 0; mt < 2; mt++) {
                        mma16816(acc[mt][j], afh[mt], bfh + 2 * t);
                        mma16816(acc[mt][j], afh[mt], bfl + 2 * t);
                        mma16816(acc[mt][j], afl[mt], bfh + 2 * t);
                    }
                }
            }
        }
    }

    // ---------------- epilogue (from fragments) ----------------
    int r_l = lane >> 2, c_l = (lane & 3) * 2;
    #pragma unroll
    for (int mt = 0; mt < 2; mt++) {
        #pragma unroll
        for (int h = 0; h < 2; h++) {
            int rr = m0 + wm * 32 + mt * 16 + h * 8 + r_l;
            if (rr >= M) continue;
            int orow = rr, prow = rr;
            if (rmode) {
                int b = rr / NPATCH, p = rr - b * NPATCH;
                orow = b * Tv + 32 + p;
                prow = 32 + p;
            }
            #pragma unroll
            for (int j = 0; j < 8; j++) {
                int col = n0 + wn * 64 + j * 8 + c_l;
                float v0 = acc[mt][j][2 * h];
                float v1 = acc[mt][j][2 * h + 1];
                if (bias)   { v0 += bias[col]; v1 += bias[col + 1]; }
                if (rowmat) { const float* rp = rowmat + (size_t)prow * ldrm + col; v0 += rp[0]; v1 += rp[1]; }
                if (accf)   { const float* op = outF + (size_t)orow * ldo + col;   v0 += op[0]; v1 += op[1]; }
                if (reluf)  { v0 = fmaxf(v0, 0.f); v1 = fmaxf(v1, 0.f); }
                if (outF)   *(float2*)(outF + (size_t)orow * ldo + col) = make_float2(v0, v1);
                if (outHi) {
                    size_t o = (size_t)rr * N + col;
                    bf_split(v0, outHi + o, outLo + o);
                    bf_split(v1, outHi + o + 1, outLo + o + 1);
                }
            }
        }
    }
}

// ---------------- fp32 GEMM (head only) ----------------
__global__ void __launch_bounds__(256, 2)
sgemm128(int M, int N, int K,
         const float* __restrict__ A, int lda,
         const float* __restrict__ B, int ldb,
         float* __restrict__ C, int ldc,
         const float* __restrict__ bias, int reluflag)
{
    __shared__ __align__(16) float As[8][128];
    __shared__ __align__(16) float Bs[8][128];
    int n0 = blockIdx.x * 128, m0 = blockIdx.y * 128;
    int tid = threadIdx.x;
    int tx = tid & 15, ty = tid >> 4;
    int arow = tid >> 1,  akk  = (tid & 1) * 4;
    int bkk  = tid >> 5,  bcol = (tid & 31) * 4;
    bool aval = (m0 + arow) < M;
    bool bval = (n0 + bcol) < N;
    const float* Aptr = A + (size_t)(m0 + arow) * lda + akk;
    const float* Bptr = B + (size_t)bkk * ldb + n0 + bcol;
    float acc[8][8];
    #pragma unroll
    for (int i = 0; i < 8; i++)
        #pragma unroll
        for (int j = 0; j < 8; j++) acc[i][j] = 0.f;
    for (int k0 = 0; k0 < K; k0 += 8) {
        float4 av = make_float4(0.f,0.f,0.f,0.f), bv = make_float4(0.f,0.f,0.f,0.f);
        if (aval) av = *(const float4*)(Aptr + k0);
        if (bval) bv = *(const float4*)(Bptr + (size_t)k0 * ldb);
        __syncthreads();
        As[akk+0][arow] = av.x; As[akk+1][arow] = av.y;
        As[akk+2][arow] = av.z; As[akk+3][arow] = av.w;
        *(float4*)&Bs[bkk][bcol] = bv;
        __syncthreads();
        #pragma unroll
        for (int kk = 0; kk < 8; kk++) {
            float a[8], b[8];
            *(float4*)(a)   = *(const float4*)&As[kk][ty*8];
            *(float4*)(a+4) = *(const float4*)&As[kk][ty*8+4];
            *(float4*)(b)   = *(const float4*)&Bs[kk][tx*8];
            *(float4*)(b+4) = *(const float4*)&Bs[kk][tx*8+4];
            #pragma unroll
            for (int i = 0; i < 8; i++)
                #pragma unroll
                for (int j = 0; j < 8; j++)
                    acc[i][j] += a[i] * b[j];
        }
    }
    #pragma unroll
    for (int i = 0; i < 8; i++) {
        int r = m0 + ty*8 + i;
        if (r >= M) continue;
        #pragma unroll
        for (int j = 0; j < 8; j++) {
            int c = n0 + tx*8 + j;
            if (c >= N) continue;
            float v = acc[i][j];
            if (bias) v += bias[c];
            if (reluflag) v = fmaxf(v, 0.f);
            C[(size_t)r * ldc + c] = v;
        }
    }
}

// ---------------- QK^T ----------------
__global__ void qk_kernel(const float* __restrict__ QKV, float* __restrict__ S) {
    int bh = blockIdx.z;
    int b = bh / Hv, h = bh % Hv;
    int t0 = blockIdx.y * 64, s0 = blockIdx.x * 64;
    __shared__ __align__(16) float Qs[64][64];
    __shared__ __align__(16) float Ks[64][64];
    const float* Qp = QKV + (size_t)b * Tv * QKVLD + h * HSv;
    const float* Kp = Qp + Ev;
    int tid = threadIdx.x;
    int row = tid >> 2, dseg = (tid & 3) * 16;
    #pragma unroll
    for (int i = 0; i < 16; i += 4) {
        float4 v = make_float4(0.f,0.f,0.f,0.f);
        if (t0 + row < Tv) v = *(const float4*)(Qp + (size_t)(t0 + row) * QKVLD + dseg + i);
        Qs[dseg+i+0][row]=v.x; Qs[dseg+i+1][row]=v.y; Qs[dseg+i+2][row]=v.z; Qs[dseg+i+3][row]=v.w;
        float4 w = make_float4(0.f,0.f,0.f,0.f);
        if (s0 + row < Tv) w = *(const float4*)(Kp + (size_t)(s0 + row) * QKVLD + dseg + i);
        Ks[dseg+i+0][row]=w.x; Ks[dseg+i+1][row]=w.y; Ks[dseg+i+2][row]=w.z; Ks[dseg+i+3][row]=w.w;
    }
    __syncthreads();
    int tx = tid & 15, ty = tid >> 4;
    float acc[4][4];
    #pragma unroll
    for (int i=0;i<4;i++) { acc[i][0]=0.f; acc[i][1]=0.f; acc[i][2]=0.f; acc[i][3]=0.f; }
    #pragma unroll 8
    for (int d = 0; d < 64; d++) {
        float4 qa = *(const float4*)&Qs[d][ty*4];
        float4 kb = *(const float4*)&Ks[d][tx*4];
        float qv[4] = {qa.x,qa.y,qa.z,qa.w};
        float kv[4] = {kb.x,kb.y,kb.z,kb.w};
        #pragma unroll
        for (int i=0;i<4;i++)
            #pragma unroll
            for (int j=0;j<4;j++) acc[i][j] += qv[i]*kv[j];
    }
    float* Sp = S + (size_t)bh * Tv * SLD;
    #pragma unroll
    for (int i=0;i<4;i++) {
        int t = t0 + ty*4 + i;
        if (t >= Tv) continue;
        #pragma unroll
        for (int j=0;j<4;j++) {
            int s = s0 + tx*4 + j;
            if (s >= Tv) continue;
            Sp[(size_t)t * SLD + s] = acc[i][j] * SCALE_QK;
        }
    }
}

// ---------------- masked softmax ----------------
__global__ void softmax_kernel(float* __restrict__ S) {
    int t = blockIdx.x, bh = blockIdx.y;
    float* row = S + ((size_t)bh * Tv + t) * SLD;
    __shared__ float red[128];
    int tid = threadIdx.x;
    float mx = -3.0e38f;
    for (int s = tid; s < Tv; s += 128)
        if (keep_fn(t, s)) mx = fmaxf(mx, row[s]);
    red[tid] = mx; __syncthreads();
    for (int off = 64; off; off >>= 1) {
        if (tid < off) red[tid] = fmaxf(red[tid], red[tid + off]);
        __syncthreads();
    }
    mx = red[0]; __syncthreads();
    float sm = 0.f;
    for (int s = tid; s < Tv; s += 128) {
        float p = keep_fn(t, s) ? expf(row[s] - mx) : 0.f;
        row[s] = p;
        sm += p;
    }
    red[tid] = sm; __syncthreads();
    for (int off = 64; off; off >>= 1) {
        if (tid < off) red[tid] += red[tid + off];
        __syncthreads();
    }
    float inv = 1.f / red[0];
    for (int s = tid; s < Tv; s += 128) row[s] *= inv;
}

// ---------------- P @ V -> O (bf16 hi/lo) ----------------
__global__ void pv_kernel(const float* __restrict__ S, const float* __restrict__ QKV,
                          bf16* __restrict__ Ohi, bf16* __restrict__ Olo) {
    int bh = blockIdx.y;
    int b = bh / Hv, h = bh % Hv;
    int t0 = blockIdx.x * 64;
    __shared__ __align__(16) float Ps[16][68];
    __shared__ __align__(16) float Vs[16][68];
    const float* Sp = S + (size_t)bh * Tv * SLD;
    const float* Vp = QKV + (size_t)b * Tv * QKVLD + 2 * Ev + h * HSv;
    int tid = threadIdx.x;
    int tr = tid >> 2,  sseg = (tid & 3) * 4;
    int sr = tid >> 4,  dcol = (tid & 15) * 4;
    int tx = tid & 15,  ty = tid >> 4;
    float acc[4][4];
    #pragma unroll
    for (int i=0;i<4;i++){ acc[i][0]=0.f; acc[i][1]=0.f; acc[i][2]=0.f; acc[i][3]=0.f; }
    for (int c0 = 0; c0 < Tv; c0 += 16) {
        float4 pv = make_float4(0.f,0.f,0.f,0.f);
        if (t0 + tr < Tv)
            pv = *(const float4*)(Sp + (size_t)(t0 + tr) * SLD + c0 + sseg);
        float4 vv = make_float4(0.f,0.f,0.f,0.f);
        if (c0 + sr < Tv)
            vv = *(const float4*)(Vp + (size_t)(c0 + sr) * QKVLD + dcol);
        __syncthreads();
        Ps[sseg+0][tr]=pv.x; Ps[sseg+1][tr]=pv.y; Ps[sseg+2][tr]=pv.z; Ps[sseg+3][tr]=pv.w;
        *(float4*)&Vs[sr][dcol] = vv;
        __syncthreads();
        #pragma unroll
        for (int ss = 0; ss < 16; ss++) {
            float4 pa = *(const float4*)&Ps[ss][ty*4];
            float4 vb = *(const float4*)&Vs[ss][tx*4];
            float pr[4] = {pa.x,pa.y,pa.z,pa.w};
            float vr[4] = {vb.x,vb.y,vb.z,vb.w};
            #pragma unroll
            for (int i=0;i<4;i++)
                #pragma unroll
                for (int j=0;j<4;j++) acc[i][j] += pr[i]*vr[j];
        }
        __syncthreads();
    }
    #pragma unroll
    for (int i=0;i<4;i++) {
        int t = t0 + ty*4 + i;
        if (t >= Tv) continue;
        #pragma unroll
        for (int j=0;j<4;j++) {
            size_t o = ((size_t)b * Tv + t) * Ev + h * HSv + tx*4 + j;
            bf_split(acc[i][j], Ohi + o, Olo + o);
        }
    }
}

// ---------------- launch ----------------
extern "C" void kernel_launch(void* const* d_in, const int* in_sizes, int n_in,
                              void* d_out, int out_size) {
    const float* images     = (const float*)d_in[0];
    const int*   goals_txt  = (const int*)  d_in[1];
    const float* goal_imgs  = (const float*)d_in[2];
    const float* patch_w    = (const float*)d_in[3];
    const float* patch_b    = (const float*)d_in[4];
    const float* text_emb   = (const float*)d_in[5];
    const float* action_emb = (const float*)d_in[6];
    const float* wq         = (const float*)d_in[7];
    const float* wk         = (const float*)d_in[8];
    const float* wv         = (const float*)d_in[9];
    const float* proj_w     = (const float*)d_in[10];
    const float* proj_b     = (const float*)d_in[11];
    const float* ln1_s      = (const float*)d_in[12];
    const float* ln1_b      = (const float*)d_in[13];
    const float* ln2_s      = (const float*)d_in[14];
    const float* ln2_b      = (const float*)d_in[15];
    const float* ff_w1      = (const float*)d_in[16];
    const float* ff_b1      = (const float*)d_in[17];
    const float* ff_w2      = (const float*)d_in[18];
    const float* ff_b2      = (const float*)d_in[19];
    const float* hw1        = (const float*)d_in[20];
    const float* hb1        = (const float*)d_in[21];
    const float* hw2        = (const float*)d_in[22];
    const float* hb2        = (const float*)d_in[23];
    float* out = (float*)d_out;

    cudaFuncSetAttribute(tgemm, cudaFuncAttributeMaxDynamicSharedMemorySize, TGSMEM);

    float *pPOS, *pX, *pQKV, *pS, *pZ;
    bf16 *pHh,*pHl,*pOh,*pOl,*pFh,*pFl,*pXPh,*pXPl;
    bf16 *pWqh,*pWql,*pWph,*pWpl,*pW1h,*pW1l,*pW2h,*pW2l,*pWth,*pWtl;
    cudaGetSymbolAddress((void**)&pPOS, g_POS);
    cudaGetSymbolAddress((void**)&pX,   g_X);
    cudaGetSymbolAddress((void**)&pQKV, g_QKV);
    cudaGetSymbolAddress((void**)&pS,   g_S);
    cudaGetSymbolAddress((void**)&pZ,   g_Z);
    cudaGetSymbolAddress((void**)&pHh,  g_Hhi);  cudaGetSymbolAddress((void**)&pHl, g_Hlo);
    cudaGetSymbolAddress((void**)&pOh,  g_Ohi);  cudaGetSymbolAddress((void**)&pOl, g_Olo);
    cudaGetSymbolAddress((void**)&pFh,  g_Fhi);  cudaGetSymbolAddress((void**)&pFl, g_Flo);
    cudaGetSymbolAddress((void**)&pXPh, g_XPhi); cudaGetSymbolAddress((void**)&pXPl,g_XPlo);
    cudaGetSymbolAddress((void**)&pWqh, g_Wqkv_h); cudaGetSymbolAddress((void**)&pWql, g_Wqkv_l);
    cudaGetSymbolAddress((void**)&pWph, g_Wprj_h); cudaGetSymbolAddress((void**)&pWpl, g_Wprj_l);
    cudaGetSymbolAddress((void**)&pW1h, g_Wf1_h);  cudaGetSymbolAddress((void**)&pW1l, g_Wf1_l);
    cudaGetSymbolAddress((void**)&pW2h, g_Wf2_h);  cudaGetSymbolAddress((void**)&pW2l, g_Wf2_l);
    cudaGetSymbolAddress((void**)&pWth, g_Wpat_h); cudaGetSymbolAddress((void**)&pWtl, g_Wpat_l);

    // ---- prep ----
    pos_kernel    <<<CDIV(Tv*Ev, 256), 256>>>(pPOS);
    conv_wqkv     <<<dim3(2, 24, Lv*3*Hv), dim3(32,8)>>>(wq, wk, wv, pWqh, pWql);
    transpose_conv<<<dim3(24, 24, Lv), dim3(32,8)>>>(proj_w, pWph, pWpl, Ev, Ev);
    transpose_conv<<<dim3(96, 24, Lv), dim3(32,8)>>>(ff_w1, pW1h, pW1l, Ev, E4);
    transpose_conv<<<dim3(24, 96, Lv), dim3(32,8)>>>(ff_w2, pW2h, pW2l, E4, Ev);
    transpose_conv<<<dim3(24, 24, 1),  dim3(32,8)>>>(patch_w, pWth, pWtl, Ev, Ev);
    gather_patches<<<CDIV(MPATCH*Ev, 256), 256>>>(images, goal_imgs, pXPh, pXPl);
    embed_txt_act <<<CDIV(Bv*33*Ev, 256), 256>>>(goals_txt, text_emb, action_emb, pPOS, pX);

    // patch embed -> X rows 32..619 (+bias +POS)
    tgemm<<<dim3(Ev/128, CDIV(MPATCH,128)), 256, TGSMEM>>>(
        MPATCH, Ev, Ev, pXPh, pXPl, pWth, pWtl,
        patch_b, pPOS, Ev, 1,
        pX, Ev, 0, 0, nullptr, nullptr);

    for (int l = 0; l < Lv; l++) {
        ln_kernel<<<MTv, 256>>>(pX, pHh, pHl, ln1_s + l*Ev, ln1_b + l*Ev);

        tgemm<<<dim3(QKVLD/128, CDIV(MTv,128)), 256, TGSMEM>>>(
            MTv, QKVLD, Ev, pHh, pHl,
            pWqh + (size_t)l*QKVLD*Ev, pWql + (size_t)l*QKVLD*Ev,
            nullptr, nullptr, 0, 0,
            pQKV, QKVLD, 0, 0, nullptr, nullptr);

        qk_kernel     <<<dim3(10, 10, Bv*Hv), 256>>>(pQKV, pS);
        softmax_kernel<<<dim3(Tv, Bv*Hv), 128>>>(pS);
        pv_kernel     <<<dim3(10, Bv*Hv), 256>>>(pS, pQKV, pOh, pOl);

        tgemm<<<dim3(Ev/128, CDIV(MTv,128)), 256, TGSMEM>>>(   // X += O @ proj + b
            MTv, Ev, Ev, pOh, pOl,
            pWph + (size_t)l*Ev*Ev, pWpl + (size_t)l*Ev*Ev,
            proj_b + l*Ev, nullptr, 0, 0,
            pX, Ev, 1, 0, nullptr, nullptr);

        ln_kernel<<<MTv, 256>>>(pX, pHh, pHl, ln2_s + l*Ev, ln2_b + l*Ev);

        tgemm<<<dim3(E4/128, CDIV(MTv,128)), 256, TGSMEM>>>(   // F = relu(h@W1+b1) -> bf16 hi/lo
            MTv, E4, Ev, pHh, pHl,
            pW1h + (size_t)l*E4*Ev, pW1l + (size_t)l*E4*Ev,
            ff_b1 + l*E4, nullptr, 0, 0,
            nullptr, 0, 0, 1, pFh, pFl);

        tgemm<<<dim3(Ev/128, CDIV(MTv,128)), 256, TGSMEM>>>(   // X += F @ W2 + b2
            MTv, Ev, E4, pFh, pFl,
            pW2h + (size_t)l*Ev*E4, pW2l + (size_t)l*Ev*E4,
            ff_b2 + l*Ev, nullptr, 0, 0,
            pX, Ev, 1, 0, nullptr, nullptr);
    }

    // head
    sgemm128<<<dim3(Ev/128, 1), 256>>>(
        Bv, Ev, Ev, pX + (size_t)620*Ev, Tv*Ev, hw1, Ev, pZ, Ev, hb1, 1);
    sgemm128<<<dim3(1, 1), 256>>>(
        Bv, AOUTv, Ev, pZ, Ev, hw2, AOUTv, out, AOUTv, hb2, 0);

    (void)in_sizes; (void)n_in; (void)out_size;
}

// round 4
// speedup vs baseline: 2.3785x; 1.7453x over previous
#include <cuda_runtime.h>
#include <cuda_bf16.h>
#include <math.h>
#include <stdint.h>
#include <stddef.h>

// ---------------- problem constants ----------------
#define Bv      16
#define Kv      2
#define Ev      768
#define Hv      12
#define HSv     64
#define Lv      12
#define Tv      621
#define TP      640          // padded T for attention tiles
#define NPATCH  588
#define QKVLD   2304
#define E4      3072
#define AOUTv   64
#define MTv     (Bv*Tv)      // 9936
#define MPATCH  (Bv*NPATCH)  // 9408
#define ZH      (Bv*Hv)      // 192
#define SCALE_QK 0.036084391824351615f

#define CDIV(a,b) (((a)+(b)-1)/(b))
#define TGSMEM   65536
#define QKSMEM   65536
#define PVSMEM   49152

typedef __nv_bfloat16 bf16;

// ---------------- scratch ----------------
__device__ __align__(128) float g_POS[Tv*Ev];
__device__ __align__(128) float g_X  [(size_t)MTv*Ev];
__device__ __align__(128) float g_S  [(size_t)ZH*TP*TP];     // scores fp32 (also dummy-gemm dump)
__device__ __align__(128) float g_Z  [Bv*Ev];

__device__ __align__(128) bf16 g_Hhi [(size_t)MTv*Ev];
__device__ __align__(128) bf16 g_Hlo [(size_t)MTv*Ev];
__device__ __align__(128) bf16 g_Ohi [(size_t)MTv*Ev];
__device__ __align__(128) bf16 g_Olo [(size_t)MTv*Ev];
__device__ __align__(128) bf16 g_Fhi [(size_t)MTv*E4];
__device__ __align__(128) bf16 g_Flo [(size_t)MTv*E4];
__device__ __align__(128) bf16 g_XPhi[(size_t)MPATCH*Ev];
__device__ __align__(128) bf16 g_XPlo[(size_t)MPATCH*Ev];
__device__ __align__(128) bf16 g_QKVh[(size_t)MTv*QKVLD];
__device__ __align__(128) bf16 g_QKVl[(size_t)MTv*QKVLD];
__device__ __align__(128) bf16 g_Ph  [(size_t)ZH*TP*TP];     // probs hi (pad rows/cols stay 0)
__device__ __align__(128) bf16 g_Pl  [(size_t)ZH*TP*TP];
__device__ __align__(128) bf16 g_Vth [(size_t)ZH*HSv*TP];    // V transposed [z][d][s]
__device__ __align__(128) bf16 g_Vtl [(size_t)ZH*HSv*TP];

__device__ __align__(128) bf16 g_Wqkv_h[(size_t)Lv*QKVLD*Ev];
__device__ __align__(128) bf16 g_Wqkv_l[(size_t)Lv*QKVLD*Ev];
__device__ __align__(128) bf16 g_Wprj_h[(size_t)Lv*Ev*Ev];
__device__ __align__(128) bf16 g_Wprj_l[(size_t)Lv*Ev*Ev];
__device__ __align__(128) bf16 g_Wf1_h [(size_t)Lv*E4*Ev];
__device__ __align__(128) bf16 g_Wf1_l [(size_t)Lv*E4*Ev];
__device__ __align__(128) bf16 g_Wf2_h [(size_t)Lv*Ev*E4];
__device__ __align__(128) bf16 g_Wf2_l [(size_t)Lv*Ev*E4];
__device__ __align__(128) bf16 g_Wpat_h[(size_t)Ev*Ev];
__device__ __align__(128) bf16 g_Wpat_l[(size_t)Ev*Ev];

// ---------------- helpers ----------------
__device__ __forceinline__ uint32_t smem_u32(const void* p) {
    uint32_t a;
    asm("{ .reg .u64 t; cvta.to.shared.u64 t, %1; cvt.u32.u64 %0, t; }" : "=r"(a) : "l"(p));
    return a;
}
__device__ __forceinline__ void cp16(uint32_t sa, const void* ga, bool v) {
    int sz = v ? 16 : 0;
    asm volatile("cp.async.cg.shared.global [%0], [%1], 16, %2;" :: "r"(sa), "l"(ga), "r"(sz) : "memory");
}
#define CP_COMMIT() asm volatile("cp.async.commit_group;" ::: "memory")
#define CP_WAIT0()  asm volatile("cp.async.wait_group 0;" ::: "memory")

#define LDSM4(r, a) \
    asm volatile("ldmatrix.sync.aligned.m8n8.x4.shared.b16 {%0,%1,%2,%3}, [%4];" \
        : "=r"((r)[0]),"=r"((r)[1]),"=r"((r)[2]),"=r"((r)[3]) : "r"(a))

__device__ __forceinline__ void mma16816(float* d, const uint32_t* a, const uint32_t* b) {
    asm volatile("mma.sync.aligned.m16n8k16.row.col.f32.bf16.bf16.f32 "
        "{%0,%1,%2,%3}, {%4,%5,%6,%7}, {%8,%9}, {%0,%1,%2,%3};"
        : "+f"(d[0]),"+f"(d[1]),"+f"(d[2]),"+f"(d[3])
        : "r"(a[0]),"r"(a[1]),"r"(a[2]),"r"(a[3]), "r"(b[0]),"r"(b[1]));
}

__device__ __forceinline__ void bf_split(float v, bf16* hi, bf16* lo) {
    bf16 h = __float2bfloat16(v);
    *hi = h;
    *lo = __float2bfloat16(v - __bfloat162float(h));
}

// ---------------- mask ----------------
__device__ __forceinline__ bool keep_fn(int t, int s) {
    bool v = (t == s);
    if (s < 32) v = !(t >= 32 && t < 228);
    if (t >= 228 && s >= 228 && s < 424) v = true;
    if (t >= 424 && s >= 424 && s < 620) v = true;
    return v;
}

// ---------------- positional embedding ----------------
__global__ void pos_kernel(float* POS) {
    int idx = blockIdx.x * 256 + threadIdx.x;
    if (idx >= Tv * Ev) return;
    int t = idx / Ev, j = idx % Ev;
    double expo = (double)(j & ~1) / (double)Ev;
    double ang  = (double)t / pow(10000.0, expo);
    POS[idx] = (float)((j & 1) ? cos(ang) : sin(ang));
}

// ---------------- transpose+convert weights ----------------
__global__ void transpose_conv(const float* __restrict__ src, bf16* __restrict__ dhi,
                               bf16* __restrict__ dlo, int R, int C) {
    __shared__ float t[32][33];
    int z = blockIdx.z;
    src += (size_t)z * R * C; dhi += (size_t)z * R * C; dlo += (size_t)z * R * C;
    int c0 = blockIdx.x * 32, r0 = blockIdx.y * 32;
    int tx = threadIdx.x, ty = threadIdx.y;
    #pragma unroll
    for (int i = 0; i < 4; i++)
        t[ty + 8*i][tx] = src[(size_t)(r0 + ty + 8*i) * C + c0 + tx];
    __syncthreads();
    #pragma unroll
    for (int i = 0; i < 4; i++) {
        float v = t[tx][ty + 8*i];
        size_t o = (size_t)(c0 + ty + 8*i) * R + r0 + tx;
        bf_split(v, dhi + o, dlo + o);
    }
}

__global__ void conv_wqkv(const float* __restrict__ wq, const float* __restrict__ wk,
                          const float* __restrict__ wv, bf16* __restrict__ dhi, bf16* __restrict__ dlo) {
    __shared__ float t[32][33];
    int z = blockIdx.z;
    int h = z % Hv, which = (z / Hv) % 3, l = z / (3 * Hv);
    const float* src = (which == 0) ? wq : (which == 1) ? wk : wv;
    src += ((size_t)l * Hv + h) * Ev * HSv;
    int d0 = blockIdx.x * 32, e0 = blockIdx.y * 32;
    int tx = threadIdx.x, ty = threadIdx.y;
    #pragma unroll
    for (int i = 0; i < 4; i++)
        t[ty + 8*i][tx] = src[(size_t)(e0 + ty + 8*i) * HSv + d0 + tx];
    __syncthreads();
    #pragma unroll
    for (int i = 0; i < 4; i++) {
        int d = d0 + ty + 8*i, e = e0 + tx;
        float v = t[tx][ty + 8*i];
        size_t o = ((size_t)l * QKVLD + which * Ev + h * HSv + d) * Ev + e;
        bf_split(v, dhi + o, dlo + o);
    }
}

// ---------------- gather patches ----------------
__global__ void gather_patches(const float* __restrict__ images, const float* __restrict__ goal_imgs,
                               bf16* __restrict__ Xhi, bf16* __restrict__ Xlo) {
    int idx = blockIdx.x * 256 + threadIdx.x;
    if (idx >= MPATCH * Ev) return;
    int f = idx % Ev;
    int r = idx / Ev;
    int p = r % NPATCH;
    int b = r / NPATCH;
    int py = f / 48, px = (f % 48) / 3, c = f % 3;
    float val;
    if (p < 196) {
        int pr = p / 14, pc = p % 14;
        int y = pr * 16 + py, x = pc * 16 + px;
        val = goal_imgs[(((size_t)b * 224 + y) * 224 + x) * 3 + c];
    } else {
        int q = p - 196;
        int k = q / 196, pp = q % 196;
        int pr = pp / 14, pc = pp % 14;
        int y = pr * 16 + py, x = pc * 16 + px;
        val = images[((((size_t)b * Kv + k) * 224 + y) * 224 + x) * 3 + c];
    }
    bf_split(val, Xhi + idx, Xlo + idx);
}

// ---------------- text + action embed (+POS) ----------------
__global__ void embed_txt_act(const int* __restrict__ goals_txt, const float* __restrict__ text_emb,
                              const float* __restrict__ action_emb, const float* __restrict__ POS,
                              float* __restrict__ X) {
    int idx = blockIdx.x * 256 + threadIdx.x;
    if (idx >= Bv * 33 * Ev) return;
    int e  = idx % Ev;
    int r  = idx / Ev;
    int tt = r % 33;
    int b  = r / 33;
    int t  = (tt < 32) ? tt : 620;
    float v = (tt < 32) ? text_emb[(size_t)goals_txt[b * 32 + tt] * Ev + e] : action_emb[e];
    X[((size_t)b * Tv + t) * Ev + e] = v + POS[(size_t)t * Ev + e];
}

// ---------------- layernorm -> hi/lo bf16 ----------------
__global__ void ln_kernel(const float* __restrict__ X, bf16* __restrict__ Ohi, bf16* __restrict__ Olo,
                          const float* __restrict__ sc, const float* __restrict__ bi) {
    int row = blockIdx.x;
    const float* x = X + (size_t)row * Ev;
    __shared__ float r1[256], r2[256];
    int tid = threadIdx.x;
    float s = 0.f, ss = 0.f;
    for (int e = tid; e < Ev; e += 256) { float v = x[e]; s += v; ss += v * v; }
    r1[tid] = s; r2[tid] = ss;
    __syncthreads();
    for (int off = 128; off; off >>= 1) {
        if (tid < off) { r1[tid] += r1[tid + off]; r2[tid] += r2[tid + off]; }
        __syncthreads();
    }
    float m   = r1[0] * (1.f / Ev);
    float var = r2[0] * (1.f / Ev) - m * m;
    float inv = 1.f / sqrtf(var + 1e-5f);
    for (int e = tid; e < Ev; e += 256) {
        float v = (x[e] - m) * inv * sc[e] + bi[e];
        size_t o = (size_t)row * Ev + e;
        bf_split(v, Ohi + o, Olo + o);
    }
}

// =====================================================================
// bf16x3 linear GEMM (mma.sync), 128x128 tile, Kc=32, term-major MMA order
// =====================================================================
__global__ void __launch_bounds__(256, 2)
tgemm(int M, int N, int K,
      const bf16* __restrict__ Ahi, const bf16* __restrict__ Alo,
      const bf16* __restrict__ Bhi, const bf16* __restrict__ Blo,
      const float* __restrict__ bias,
      const float* __restrict__ rowmat, int ldrm, int rmode,
      float* outF, int ldo, int accf, int reluf,
      bf16* outHi, bf16* outLo)
{
    extern __shared__ char sm[];
    uint32_t sbase = smem_u32(sm);
    int tid = threadIdx.x, lane = tid & 31, wid = tid >> 5;
    int m0 = blockIdx.y * 128, n0 = blockIdx.x * 128;
    int wm = wid & 3, wn = wid >> 2;

    float acc[2][8][4];
    #pragma unroll
    for (int i = 0; i < 2; i++)
        #pragma unroll
        for (int j = 0; j < 8; j++)
            #pragma unroll
            for (int q = 0; q < 4; q++) acc[i][j][q] = 0.f;

    int nc = K >> 5;

    auto ld_st = [&](int c, int st) {
        uint32_t sb = sbase + st * 32768;
        int k0 = c * 32;
        #pragma unroll
        for (int h2 = 0; h2 < 2; h2++) {
            int u = h2 * 256 + tid;
            int row = u >> 2, seg = u & 3;
            uint32_t off = (uint32_t)(row * 64 + ((seg ^ ((row >> 1) & 3)) << 4));
            bool av = (m0 + row) < M;
            size_t ao = (size_t)(av ? (m0 + row) : 0) * K + k0 + seg * 8;
            size_t bo = (size_t)(n0 + row) * K + k0 + seg * 8;
            cp16(sb + off,         Ahi + ao, av);
            cp16(sb + 8192  + off, Alo + ao, av);
            cp16(sb + 16384 + off, Bhi + bo, true);
            cp16(sb + 24576 + off, Blo + bo, true);
        }
        CP_COMMIT();
    };

    ld_st(0, 0);

    for (int c = 0; c < nc; c++) {
        int s = c & 1;
        CP_WAIT0();
        __syncthreads();
        if (c + 1 < nc) ld_st(c + 1, 1 - s);

        uint32_t sA_hi = sbase + s * 32768;
        uint32_t sA_lo = sA_hi + 8192;
        uint32_t sB_hi = sA_hi + 16384;
        uint32_t sB_lo = sA_hi + 24576;

        #pragma unroll
        for (int ks = 0; ks < 2; ks++) {
            uint32_t afh[2][4], afl[2][4];
            #pragma unroll
            for (int mt = 0; mt < 2; mt++) {
                int matA = lane >> 3;
                int arow = wm * 32 + mt * 16 + (lane & 7) + (matA & 1) * 8;
                int aseg = ks * 2 + (matA >> 1);
                uint32_t off = (uint32_t)(arow * 64 + ((aseg ^ ((arow >> 1) & 3)) << 4));
                LDSM4(afh[mt], sA_hi + off);
                LDSM4(afl[mt], sA_lo + off);
            }
            #pragma unroll
            for (int np = 0; np < 4; np++) {
                uint32_t bfh[4], bfl[4];
                int matB = lane >> 3;
                int brow = wn * 64 + np * 16 + ((matB >> 1) << 3) + (lane & 7);
                int bseg = ks * 2 + (matB & 1);
                uint32_t boff = (uint32_t)(brow * 64 + ((bseg ^ ((brow >> 1) & 3)) << 4));
                LDSM4(bfh, sB_hi + boff);
                LDSM4(bfl, sB_lo + boff);
                // term-major: 4 independent MMAs per group
                #pragma unroll
                for (int t = 0; t < 2; t++)
                    #pragma unroll
                    for (int mt = 0; mt < 2; mt++)
                        mma16816(acc[mt][np * 2 + t], afh[mt], bfh + 2 * t);
                #pragma unroll
                for (int t = 0; t < 2; t++)
                    #pragma unroll
                    for (int mt = 0; mt < 2; mt++)
                        mma16816(acc[mt][np * 2 + t], afh[mt], bfl + 2 * t);
                #pragma unroll
                for (int t = 0; t < 2; t++)
                    #pragma unroll
                    for (int mt = 0; mt < 2; mt++)
                        mma16816(acc[mt][np * 2 + t], afl[mt], bfh + 2 * t);
            }
        }
    }

    int r_l = lane >> 2, c_l = (lane & 3) * 2;
    #pragma unroll
    for (int mt = 0; mt < 2; mt++) {
        #pragma unroll
        for (int h = 0; h < 2; h++) {
            int rr = m0 + wm * 32 + mt * 16 + h * 8 + r_l;
            if (rr >= M) continue;
            int orow = rr, prow = rr;
            if (rmode) {
                int b = rr / NPATCH, p = rr - b * NPATCH;
                orow = b * Tv + 32 + p;
                prow = 32 + p;
            }
            #pragma unroll
            for (int j = 0; j < 8; j++) {
                int col = n0 + wn * 64 + j * 8 + c_l;
                float v0 = acc[mt][j][2 * h];
                float v1 = acc[mt][j][2 * h + 1];
                if (bias)   { v0 += bias[col]; v1 += bias[col + 1]; }
                if (rowmat) { const float* rp = rowmat + (size_t)prow * ldrm + col; v0 += rp[0]; v1 += rp[1]; }
                if (accf)   { const float* op = outF + (size_t)orow * ldo + col;   v0 += op[0]; v1 += op[1]; }
                if (reluf)  { v0 = fmaxf(v0, 0.f); v1 = fmaxf(v1, 0.f); }
                if (outF)   *(float2*)(outF + (size_t)orow * ldo + col) = make_float2(v0, v1);
                if (outHi) {
                    size_t o = (size_t)rr * N + col;
                    bf_split(v0, outHi + o, outLo + o);
                    bf_split(v1, outHi + o + 1, outLo + o + 1);
                }
            }
        }
    }
}

// =====================================================================
// qk_mma: S[z][t][s] = (Q K^T)*scale ; 128x128 tile, K=64 one-shot
// =====================================================================
__global__ void __launch_bounds__(256, 2)
qk_mma(const bf16* __restrict__ Qh, const bf16* __restrict__ Ql, float* __restrict__ S)
{
    extern __shared__ char sm[];
    uint32_t sbase = smem_u32(sm);     // +0 Qhi, +16K Qlo, +32K Khi, +48K Klo (128 rows x 128B)
    int tid = threadIdx.x, lane = tid & 31, wid = tid >> 5;
    int z = blockIdx.z, b = z / Hv, h = z % Hv;
    int t0 = blockIdx.y * 128, s0 = blockIdx.x * 128;

    #pragma unroll
    for (int i = 0; i < 4; i++) {
        int u = i * 256 + tid;
        int row = u >> 3, seg = u & 7;
        uint32_t off = (uint32_t)(row * 128 + ((seg ^ (row & 7)) << 4));
        bool qv = (t0 + row) < Tv;
        bool kv = (s0 + row) < Tv;
        size_t qo = (size_t)(b * Tv + (qv ? t0 + row : 0)) * QKVLD + h * HSv + seg * 8;
        size_t ko = (size_t)(b * Tv + (kv ? s0 + row : 0)) * QKVLD + Ev + h * HSv + seg * 8;
        cp16(sbase + off,         Qh + qo, qv);
        cp16(sbase + 16384 + off, Ql + qo, qv);
        cp16(sbase + 32768 + off, Qh + ko, kv);
        cp16(sbase + 49152 + off, Ql + ko, kv);
    }
    CP_COMMIT();
    CP_WAIT0();
    __syncthreads();

    int wm = wid & 3, wn = wid >> 2;
    float acc[2][8][4];
    #pragma unroll
    for (int i = 0; i < 2; i++)
        #pragma unroll
        for (int j = 0; j < 8; j++)
            #pragma unroll
            for (int q = 0; q < 4; q++) acc[i][j][q] = 0.f;

    #pragma unroll
    for (int ks = 0; ks < 4; ks++) {
        uint32_t afh[2][4], afl[2][4];
        #pragma unroll
        for (int mt = 0; mt < 2; mt++) {
            int matA = lane >> 3;
            int arow = wm * 32 + mt * 16 + (lane & 7) + (matA & 1) * 8;
            int aseg = ks * 2 + (matA >> 1);
            uint32_t off = (uint32_t)(arow * 128 + ((aseg ^ (arow & 7)) << 4));
            LDSM4(afh[mt], sbase + off);
            LDSM4(afl[mt], sbase + 16384 + off);
        }
        #pragma unroll
        for (int np = 0; np < 4; np++) {
            uint32_t bfh[4], bfl[4];
            int matB = lane >> 3;
            int brow = wn * 64 + np * 16 + ((matB >> 1) << 3) + (lane & 7);
            int bseg = ks * 2 + (matB & 1);
            uint32_t boff = (uint32_t)(brow * 128 + ((bseg ^ (brow & 7)) << 4));
            LDSM4(bfh, sbase + 32768 + boff);
            LDSM4(bfl, sbase + 49152 + boff);
            #pragma unroll
            for (int t = 0; t < 2; t++)
                #pragma unroll
                for (int mt = 0; mt < 2; mt++)
                    mma16816(acc[mt][np * 2 + t], afh[mt], bfh + 2 * t);
            #pragma unroll
            for (int t = 0; t < 2; t++)
                #pragma unroll
                for (int mt = 0; mt < 2; mt++)
                    mma16816(acc[mt][np * 2 + t], afh[mt], bfl + 2 * t);
            #pragma unroll
            for (int t = 0; t < 2; t++)
                #pragma unroll
                for (int mt = 0; mt < 2; mt++)
                    mma16816(acc[mt][np * 2 + t], afl[mt], bfh + 2 * t);
        }
    }

    int r_l = lane >> 2, c_l = (lane & 3) * 2;
    #pragma unroll
    for (int mt = 0; mt < 2; mt++)
        #pragma unroll
        for (int h2 = 0; h2 < 2; h2++) {
            int rr = t0 + wm * 32 + mt * 16 + h2 * 8 + r_l;
            #pragma unroll
            for (int j = 0; j < 8; j++) {
                int col = s0 + wn * 64 + j * 8 + c_l;
                float2 v = make_float2(acc[mt][j][2 * h2] * SCALE_QK,
                                       acc[mt][j][2 * h2 + 1] * SCALE_QK);
                *(float2*)(S + ((size_t)z * TP + rr) * TP + col) = v;
            }
        }
}

// ---------------- masked softmax: S fp32 -> P hi/lo bf16 (cols padded 0) ----------------
__global__ void softmax_kernel(const float* __restrict__ S,
                               bf16* __restrict__ Ph, bf16* __restrict__ Pl)
{
    int t = blockIdx.x, z = blockIdx.y;
    const float* row = S + ((size_t)z * TP + t) * TP;
    bf16* ph = Ph + ((size_t)z * TP + t) * TP;
    bf16* pl = Pl + ((size_t)z * TP + t) * TP;
    __shared__ float red[256];
    int tid = threadIdx.x;
    float mx = -3.0e38f;
    #pragma unroll
    for (int i = 0; i < 3; i++) {
        int s = tid + i * 256;
        if (s < TP && keep_fn(t, s)) mx = fmaxf(mx, row[s]);
    }
    red[tid] = mx; __syncthreads();
    for (int off = 128; off; off >>= 1) {
        if (tid < off) red[tid] = fmaxf(red[tid], red[tid + off]);
        __syncthreads();
    }
    mx = red[0]; __syncthreads();
    float pv[3]; float sum = 0.f;
    #pragma unroll
    for (int i = 0; i < 3; i++) {
        int s = tid + i * 256;
        float p = 0.f;
        if (s < TP && keep_fn(t, s)) p = expf(row[s] - mx);
        pv[i] = p; sum += p;
    }
    red[tid] = sum; __syncthreads();
    for (int off = 128; off; off >>= 1) {
        if (tid < off) red[tid] += red[tid + off];
        __syncthreads();
    }
    float inv = 1.f / red[0];
    #pragma unroll
    for (int i = 0; i < 3; i++) {
        int s = tid + i * 256;
        if (s < TP) bf_split(pv[i] * inv, ph + s, pl + s);
    }
}

// ---------------- V repack: QKV v-part -> Vt[z][d][s] hi/lo (s padded 0) ----------------
__global__ void repack_v(const bf16* __restrict__ Qh, const bf16* __restrict__ Ql,
                         bf16* __restrict__ Vth, bf16* __restrict__ Vtl)
{
    __shared__ bf16 th[32][33], tl[32][33];
    int z = blockIdx.z, b = z / Hv, h = z % Hv;
    int s0 = blockIdx.x * 32, d0 = blockIdx.y * 32;
    int tx = threadIdx.x, ty = threadIdx.y;
    #pragma unroll
    for (int i = 0; i < 4; i++) {
        int s = s0 + ty + 8 * i;
        bf16 vh = __float2bfloat16(0.f), vl = vh;
        if (s < Tv) {
            size_t o = (size_t)(b * Tv + s) * QKVLD + 2 * Ev + h * HSv + d0 + tx;
            vh = Qh[o]; vl = Ql[o];
        }
        th[ty + 8 * i][tx] = vh;
        tl[ty + 8 * i][tx] = vl;
    }
    __syncthreads();
    #pragma unroll
    for (int i = 0; i < 4; i++) {
        size_t o = ((size_t)z * HSv + d0 + ty + 8 * i) * TP + s0 + tx;
        Vth[o] = th[tx][ty + 8 * i];
        Vtl[o] = tl[tx][ty + 8 * i];
    }
}

// =====================================================================
// pv_mma: O[z][t][d] = P @ V^T-layout ; tile 128x64, Kc=32, 20 chunks
// =====================================================================
__global__ void __launch_bounds__(256, 2)
pv_mma(const bf16* __restrict__ Ph, const bf16* __restrict__ Pl,
       const bf16* __restrict__ Vth, const bf16* __restrict__ Vtl,
       bf16* __restrict__ Ohi, bf16* __restrict__ Olo)
{
    extern __shared__ char sm[];
    uint32_t sbase = smem_u32(sm);   // stage: +0 Phi(16K? no: 128x64B=8K), layout below
    // stage layout (24KB): +0 P_hi 8K, +8K P_lo 8K, +16K V_hi 4K, +20K V_lo 4K
    int tid = threadIdx.x, lane = tid & 31, wid = tid >> 5;
    int z = blockIdx.y, b = z / Hv, h = z % Hv;
    int t0 = blockIdx.x * 128;
    int wm = wid & 3, wn = wid >> 2;

    float acc[2][4][4];
    #pragma unroll
    for (int i = 0; i < 2; i++)
        #pragma unroll
        for (int j = 0; j < 4; j++)
            #pragma unroll
            for (int q = 0; q < 4; q++) acc[i][j][q] = 0.f;

    auto ld_st = [&](int c, int st) {
        uint32_t sb = sbase + st * 24576;
        int k0 = c * 32;
        {   // P: 128 rows x 4 segs, hi+lo -> 2 cp16/thread each
            int u = tid;
            int row = u >> 1, seg0 = (u & 1) * 2;
            #pragma unroll
            for (int q = 0; q < 2; q++) {
                int seg = seg0 + q;
                uint32_t off = (uint32_t)(row * 64 + ((seg ^ ((row >> 1) & 3)) << 4));
                size_t po = ((size_t)z * TP + t0 + row) * TP + k0 + seg * 8;
                cp16(sb + off,        Ph + po, true);
                cp16(sb + 8192 + off, Pl + po, true);
            }
        }
        {   // V: 64 rows x 4 segs = 256 -> 1 cp16/thread each
            int row = tid >> 2, seg = tid & 3;
            uint32_t off = (uint32_t)(row * 64 + ((seg ^ ((row >> 1) & 3)) << 4));
            size_t vo = ((size_t)z * HSv + row) * TP + k0 + seg * 8;
            cp16(sb + 16384 + off, Vth + vo, true);
            cp16(sb + 20480 + off, Vtl + vo, true);
        }
        CP_COMMIT();
    };

    ld_st(0, 0);

    for (int c = 0; c < TP / 32; c++) {
        int s = c & 1;
        CP_WAIT0();
        __syncthreads();
        if (c + 1 < TP / 32) ld_st(c + 1, 1 - s);

        uint32_t sP_hi = sbase + s * 24576;
        uint32_t sP_lo = sP_hi + 8192;
        uint32_t sV_hi = sP_hi + 16384;
        uint32_t sV_lo = sP_hi + 20480;

        #pragma unroll
        for (int ks = 0; ks < 2; ks++) {
            uint32_t afh[2][4], afl[2][4];
            #pragma unroll
            for (int mt = 0; mt < 2; mt++) {
                int matA = lane >> 3;
                int arow = wm * 32 + mt * 16 + (lane & 7) + (matA & 1) * 8;
                int aseg = ks * 2 + (matA >> 1);
                uint32_t off = (uint32_t)(arow * 64 + ((aseg ^ ((arow >> 1) & 3)) << 4));
                LDSM4(afh[mt], sP_hi + off);
                LDSM4(afl[mt], sP_lo + off);
            }
            #pragma unroll
            for (int np = 0; np < 2; np++) {
                uint32_t bfh[4], bfl[4];
                int matB = lane >> 3;
                int brow = wn * 32 + np * 16 + ((matB >> 1) << 3) + (lane & 7);
                int bseg = ks * 2 + (matB & 1);
                uint32_t boff = (uint32_t)(brow * 64 + ((bseg ^ ((brow >> 1) & 3)) << 4));
                LDSM4(bfh, sV_hi + boff);
                LDSM4(bfl, sV_lo + boff);
                #pragma unroll
                for (int t = 0; t < 2; t++)
                    #pragma unroll
                    for (int mt = 0; mt < 2; mt++)
                        mma16816(acc[mt][np * 2 + t], afh[mt], bfh + 2 * t);
                #pragma unroll
                for (int t = 0; t < 2; t++)
                    #pragma unroll
                    for (int mt = 0; mt < 2; mt++)
                        mma16816(acc[mt][np * 2 + t], afh[mt], bfl + 2 * t);
                #pragma unroll
                for (int t = 0; t < 2; t++)
                    #pragma unroll
                    for (int mt = 0; mt < 2; mt++)
                        mma16816(acc[mt][np * 2 + t], afl[mt], bfh + 2 * t);
            }
        }
    }

    int r_l = lane >> 2, c_l = (lane & 3) * 2;
    #pragma unroll
    for (int mt = 0; mt < 2; mt++)
        #pragma unroll
        for (int h2 = 0; h2 < 2; h2++) {
            int rr = t0 + wm * 32 + mt * 16 + h2 * 8 + r_l;
            if (rr >= Tv) continue;
            #pragma unroll
            for (int j = 0; j < 4; j++) {
                int col = wn * 32 + j * 8 + c_l;
                size_t o = ((size_t)(b * Tv + rr)) * Ev + h * HSv + col;
                bf_split(acc[mt][j][2 * h2],     Ohi + o,     Olo + o);
                bf_split(acc[mt][j][2 * h2 + 1], Ohi + o + 1, Olo + o + 1);
            }
        }
}

// ---------------- fp32 GEMM (head only) ----------------
__global__ void __launch_bounds__(256, 2)
sgemm128(int M, int N, int K,
         const float* __restrict__ A, int lda,
         const float* __restrict__ B, int ldb,
         float* __restrict__ C, int ldc,
         const float* __restrict__ bias, int reluflag)
{
    __shared__ __align__(16) float As[8][128];
    __shared__ __align__(16) float Bs[8][128];
    int n0 = blockIdx.x * 128, m0 = blockIdx.y * 128;
    int tid = threadIdx.x;
    int tx = tid & 15, ty = tid >> 4;
    int arow = tid >> 1,  akk  = (tid & 1) * 4;
    int bkk  = tid >> 5,  bcol = (tid & 31) * 4;
    bool aval = (m0 + arow) < M;
    bool bval = (n0 + bcol) < N;
    const float* Aptr = A + (size_t)(m0 + arow) * lda + akk;
    const float* Bptr = B + (size_t)bkk * ldb + n0 + bcol;
    float acc[8][8];
    #pragma unroll
    for (int i = 0; i < 8; i++)
        #pragma unroll
        for (int j = 0; j < 8; j++) acc[i][j] = 0.f;
    for (int k0 = 0; k0 < K; k0 += 8) {
        float4 av = make_float4(0.f,0.f,0.f,0.f), bv = make_float4(0.f,0.f,0.f,0.f);
        if (aval) av = *(const float4*)(Aptr + k0);
        if (bval) bv = *(const float4*)(Bptr + (size_t)k0 * ldb);
        __syncthreads();
        As[akk+0][arow] = av.x; As[akk+1][arow] = av.y;
        As[akk+2][arow] = av.z; As[akk+3][arow] = av.w;
        *(float4*)&Bs[bkk][bcol] = bv;
        __syncthreads();
        #pragma unroll
        for (int kk = 0; kk < 8; kk++) {
            float a[8], b2[8];
            *(float4*)(a)    = *(const float4*)&As[kk][ty*8];
            *(float4*)(a+4)  = *(const float4*)&As[kk][ty*8+4];
            *(float4*)(b2)   = *(const float4*)&Bs[kk][tx*8];
            *(float4*)(b2+4) = *(const float4*)&Bs[kk][tx*8+4];
            #pragma unroll
            for (int i = 0; i < 8; i++)
                #pragma unroll
                for (int j = 0; j < 8; j++)
                    acc[i][j] += a[i] * b2[j];
        }
    }
    #pragma unroll
    for (int i = 0; i < 8; i++) {
        int r = m0 + ty*8 + i;
        if (r >= M) continue;
        #pragma unroll
        for (int j = 0; j < 8; j++) {
            int c = n0 + tx*8 + j;
            if (c >= N) continue;
            float v = acc[i][j];
            if (bias) v += bias[c];
            if (reluflag) v = fmaxf(v, 0.f);
            C[(size_t)r * ldc + c] = v;
        }
    }
}

// ---------------- launch ----------------
extern "C" void kernel_launch(void* const* d_in, const int* in_sizes, int n_in,
                              void* d_out, int out_size) {
    const float* images     = (const float*)d_in[0];
    const int*   goals_txt  = (const int*)  d_in[1];
    const float* goal_imgs  = (const float*)d_in[2];
    const float* patch_w    = (const float*)d_in[3];
    const float* patch_b    = (const float*)d_in[4];
    const float* text_emb   = (const float*)d_in[5];
    const float* action_emb = (const float*)d_in[6];
    const float* wq         = (const float*)d_in[7];
    const float* wk         = (const float*)d_in[8];
    const float* wv         = (const float*)d_in[9];
    const float* proj_w     = (const float*)d_in[10];
    const float* proj_b     = (const float*)d_in[11];
    const float* ln1_s      = (const float*)d_in[12];
    const float* ln1_b      = (const float*)d_in[13];
    const float* ln2_s      = (const float*)d_in[14];
    const float* ln2_b      = (const float*)d_in[15];
    const float* ff_w1      = (const float*)d_in[16];
    const float* ff_b1      = (const float*)d_in[17];
    const float* ff_w2      = (const float*)d_in[18];
    const float* ff_b2      = (const float*)d_in[19];
    const float* hw1        = (const float*)d_in[20];
    const float* hb1        = (const float*)d_in[21];
    const float* hw2        = (const float*)d_in[22];
    const float* hb2        = (const float*)d_in[23];
    float* out = (float*)d_out;

    cudaFuncSetAttribute(tgemm,  cudaFuncAttributeMaxDynamicSharedMemorySize, TGSMEM);
    cudaFuncSetAttribute(qk_mma, cudaFuncAttributeMaxDynamicSharedMemorySize, QKSMEM);
    cudaFuncSetAttribute(pv_mma, cudaFuncAttributeMaxDynamicSharedMemorySize, PVSMEM);

    float *pPOS, *pX, *pS, *pZ;
    bf16 *pHh,*pHl,*pOh,*pOl,*pFh,*pFl,*pXPh,*pXPl,*pQh,*pQl,*pPh,*pPl,*pVth,*pVtl;
    bf16 *pWqh,*pWql,*pWph,*pWpl,*pW1h,*pW1l,*pW2h,*pW2l,*pWth,*pWtl;
    cudaGetSymbolAddress((void**)&pPOS, g_POS);
    cudaGetSymbolAddress((void**)&pX,   g_X);
    cudaGetSymbolAddress((void**)&pS,   g_S);
    cudaGetSymbolAddress((void**)&pZ,   g_Z);
    cudaGetSymbolAddress((void**)&pHh,  g_Hhi);  cudaGetSymbolAddress((void**)&pHl, g_Hlo);
    cudaGetSymbolAddress((void**)&pOh,  g_Ohi);  cudaGetSymbolAddress((void**)&pOl, g_Olo);
    cudaGetSymbolAddress((void**)&pFh,  g_Fhi);  cudaGetSymbolAddress((void**)&pFl, g_Flo);
    cudaGetSymbolAddress((void**)&pXPh, g_XPhi); cudaGetSymbolAddress((void**)&pXPl,g_XPlo);
    cudaGetSymbolAddress((void**)&pQh,  g_QKVh); cudaGetSymbolAddress((void**)&pQl, g_QKVl);
    cudaGetSymbolAddress((void**)&pPh,  g_Ph);   cudaGetSymbolAddress((void**)&pPl, g_Pl);
    cudaGetSymbolAddress((void**)&pVth, g_Vth);  cudaGetSymbolAddress((void**)&pVtl,g_Vtl);
    cudaGetSymbolAddress((void**)&pWqh, g_Wqkv_h); cudaGetSymbolAddress((void**)&pWql, g_Wqkv_l);
    cudaGetSymbolAddress((void**)&pWph, g_Wprj_h); cudaGetSymbolAddress((void**)&pWpl, g_Wprj_l);
    cudaGetSymbolAddress((void**)&pW1h, g_Wf1_h);  cudaGetSymbolAddress((void**)&pW1l, g_Wf1_l);
    cudaGetSymbolAddress((void**)&pW2h, g_Wf2_h);  cudaGetSymbolAddress((void**)&pW2l, g_Wf2_l);
    cudaGetSymbolAddress((void**)&pWth, g_Wpat_h); cudaGetSymbolAddress((void**)&pWtl, g_Wpat_l);

    // ---- prep (ordered so launch #6 is a representative tgemm for ncu -s 5 -c 1) ----
    pos_kernel    <<<CDIV(Tv*Ev, 256), 256>>>(pPOS);                                  // 1
    conv_wqkv     <<<dim3(2, 24, Lv*3*Hv), dim3(32,8)>>>(wq, wk, wv, pWqh, pWql);     // 2
    transpose_conv<<<dim3(24, 24, Lv), dim3(32,8)>>>(proj_w, pWph, pWpl, Ev, Ev);     // 3
    transpose_conv<<<dim3(96, 24, Lv), dim3(32,8)>>>(ff_w1, pW1h, pW1l, Ev, E4);      // 4
    transpose_conv<<<dim3(24, 96, Lv), dim3(32,8)>>>(ff_w2, pW2h, pW2l, E4, Ev);      // 5
    // 6: dummy QKV-shaped tgemm (deterministic; output scratch overwritten later)
    tgemm<<<dim3(QKVLD/128, CDIV(MPATCH,128)), 256, TGSMEM>>>(                         // 6
        MPATCH, QKVLD, Ev, pXPh, pXPl, pWqh, pWql,
        nullptr, nullptr, 0, 0, pS, QKVLD, 0, 0, nullptr, nullptr);
    transpose_conv<<<dim3(24, 24, 1),  dim3(32,8)>>>(patch_w, pWth, pWtl, Ev, Ev);
    gather_patches<<<CDIV(MPATCH*Ev, 256), 256>>>(images, goal_imgs, pXPh, pXPl);
    embed_txt_act <<<CDIV(Bv*33*Ev, 256), 256>>>(goals_txt, text_emb, action_emb, pPOS, pX);

    // patch embed -> X rows 32..619 (+bias +POS)
    tgemm<<<dim3(Ev/128, CDIV(MPATCH,128)), 256, TGSMEM>>>(
        MPATCH, Ev, Ev, pXPh, pXPl, pWth, pWtl,
        patch_b, pPOS, Ev, 1,
        pX, Ev, 0, 0, nullptr, nullptr);

    for (int l = 0; l < Lv; l++) {
        ln_kernel<<<MTv, 256>>>(pX, pHh, pHl, ln1_s + l*Ev, ln1_b + l*Ev);

        tgemm<<<dim3(QKVLD/128, CDIV(MTv,128)), 256, TGSMEM>>>(   // QKV -> bf16 hi/lo
            MTv, QKVLD, Ev, pHh, pHl,
            pWqh + (size_t)l*QKVLD*Ev, pWql + (size_t)l*QKVLD*Ev,
            nullptr, nullptr, 0, 0,
            nullptr, 0, 0, 0, pQh, pQl);

        qk_mma        <<<dim3(TP/128, TP/128, ZH), 256, QKSMEM>>>(pQh, pQl, pS);
        softmax_kernel<<<dim3(Tv, ZH), 256>>>(pS, pPh, pPl);
        repack_v      <<<dim3(TP/32, HSv/32, ZH), dim3(32,8)>>>(pQh, pQl, pVth, pVtl);
        pv_mma        <<<dim3(TP/128, ZH), 256, PVSMEM>>>(pPh, pPl, pVth, pVtl, pOh, pOl);

        tgemm<<<dim3(Ev/128, CDIV(MTv,128)), 256, TGSMEM>>>(   // X += O @ proj + b
            MTv, Ev, Ev, pOh, pOl,
            pWph + (size_t)l*Ev*Ev, pWpl + (size_t)l*Ev*Ev,
            proj_b + l*Ev, nullptr, 0, 0,
            pX, Ev, 1, 0, nullptr, nullptr);

        ln_kernel<<<MTv, 256>>>(pX, pHh, pHl, ln2_s + l*Ev, ln2_b + l*Ev);

        tgemm<<<dim3(E4/128, CDIV(MTv,128)), 256, TGSMEM>>>(   // F = relu(h@W1+b1)
            MTv, E4, Ev, pHh, pHl,
            pW1h + (size_t)l*E4*Ev, pW1l + (size_t)l*E4*Ev,
            ff_b1 + l*E4, nullptr, 0, 0,
            nullptr, 0, 0, 1, pFh, pFl);

        tgemm<<<dim3(Ev/128, CDIV(MTv,128)), 256, TGSMEM>>>(   // X += F @ W2 + b2
            MTv, Ev, E4, pFh, pFl,
            pW2h + (size_t)l*Ev*E4, pW2l + (size_t)l*Ev*E4,
            ff_b2 + l*Ev, nullptr, 0, 0,
            pX, Ev, 1, 0, nullptr, nullptr);
    }

    // head
    sgemm128<<<dim3(Ev/128, 1), 256>>>(
        Bv, Ev, Ev, pX + (size_t)620*Ev, Tv*Ev, hw1, Ev, pZ, Ev, hb1, 1);
    sgemm128<<<dim3(1, 1), 256>>>(
        Bv, AOUTv, Ev, pZ, Ev, hw2, AOUTv, out, AOUTv, hb2, 0);

    (void)in_sizes; (void)n_in; (void)out_size;
}